// round 16
// baseline (speedup 1.0000x reference)
#include <cuda_runtime.h>
#include <cstdint>

#define N_NODES     8192
#define N_PAIRS_MAX 1000000
#define PATH_LEN    8
#define EDGE_DIM    16
#define MAX_EDGES   100000
#define ROW_CAP     512         // Poisson mean 122/row; 512 unreachable

// Record packing: [p+1 : 20][col : 13][val>>1 : 31]
//  - max over same-cell records == max over p+1 (top bits; col equal)
//  - val reconstructed as (low31 << 1): drops fp32 mantissa LSB (<=1 ulp)
__device__ float              g_T[MAX_EDGES * PATH_LEN];        // 3.2 MB
__device__ unsigned           g_cursor[N_NODES];                // 32 KB
__device__ unsigned long long g_rec[(size_t)N_NODES * ROW_CAP]; // 32 MB
__device__ unsigned           g_scatter_done;                   // block counter

__device__ __forceinline__ void gdc_wait() {
    asm volatile("griddepcontrol.wait;" ::: "memory");
}
__device__ __forceinline__ void gdc_launch_dependents() {
    asm volatile("griddepcontrol.launch_dependents;" ::: "memory");
}

// ---------------------------------------------------------------------------
// T[e][l] = dot(edge_attr[e], edge_vector[l]) / PATH_LEN.
// Also zeroes cursor and resets the scatter-done counter (safe: scatter only
// increments after gdc_wait on this grid).
// ---------------------------------------------------------------------------
__global__ void __launch_bounds__(256)
precompute_T(const float* __restrict__ edge_attr,
             const float* __restrict__ edge_vector,
             int n_edges)
{
    gdc_launch_dependents();

    int e = blockIdx.x * blockDim.x + threadIdx.x;
    if (e == 0) g_scatter_done = 0u;
    if (e < N_NODES) g_cursor[e] = 0u;
    if (e >= n_edges) return;

    const float4* ea = (const float4*)edge_attr + (size_t)e * 4;
    float4 a0 = __ldg(&ea[0]), a1 = __ldg(&ea[1]);
    float4 a2 = __ldg(&ea[2]), a3 = __ldg(&ea[3]);

    const float4* ev = (const float4*)edge_vector;
    float t[PATH_LEN];
#pragma unroll
    for (int l = 0; l < PATH_LEN; ++l) {
        float4 v0 = __ldg(&ev[l * 4 + 0]);
        float4 v1 = __ldg(&ev[l * 4 + 1]);
        float4 v2 = __ldg(&ev[l * 4 + 2]);
        float4 v3 = __ldg(&ev[l * 4 + 3]);
        float d = a0.x * v0.x + a0.y * v0.y + a0.z * v0.z + a0.w * v0.w
                + a1.x * v1.x + a1.y * v1.y + a1.z * v1.z + a1.w * v1.w
                + a2.x * v2.x + a2.y * v2.y + a2.z * v2.z + a2.w * v2.w
                + a3.x * v3.x + a3.y * v3.y + a3.z * v3.z + a3.w * v3.w;
        t[l] = d * (1.0f / PATH_LEN);
    }
    float4* tt = (float4*)(g_T + (size_t)e * PATH_LEN);
    tt[0] = make_float4(t[0], t[1], t[2], t[3]);
    tt[1] = make_float4(t[4], t[5], t[6], t[7]);
}

// ---------------------------------------------------------------------------
// 4 pairs per thread. Fires launch_dependents AT ENTRY so the fill kernel
// (next in PDL chain) co-runs with the gather phase. Signals completion via
// g_scatter_done (release) for the fixup spin.
// ---------------------------------------------------------------------------
__global__ void __launch_bounds__(256)
scatter_dots4(const int* __restrict__ paths,
              const int* __restrict__ src,
              const int* __restrict__ dst,
              int n_pairs)
{
    gdc_launch_dependents();     // fill starts zeroing output NOW

    int t  = blockIdx.x * blockDim.x + threadIdx.x;
    int p0 = t * 4;
    int nrem = n_pairs - p0;     // may be <= 0

    int4 pr[8];
    int s[4], d[4];
    if (nrem > 0) {
        const int4* pp = (const int4*)paths + (size_t)p0 * 2;
#pragma unroll
        for (int k = 0; k < 4; ++k) {
            if (k < nrem) {
                pr[2 * k + 0] = __ldg(&pp[2 * k + 0]);
                pr[2 * k + 1] = __ldg(&pp[2 * k + 1]);
            } else {
                pr[2 * k + 0] = make_int4(-1, -1, -1, -1);
                pr[2 * k + 1] = make_int4(-1, -1, -1, -1);
            }
        }
        if (nrem >= 4) {
            int4 s4 = __ldg((const int4*)(src + p0));
            int4 d4 = __ldg((const int4*)(dst + p0));
            s[0] = s4.x; s[1] = s4.y; s[2] = s4.z; s[3] = s4.w;
            d[0] = d4.x; d[1] = d4.y; d[2] = d4.z; d[3] = d4.w;
        } else {
#pragma unroll
            for (int k = 0; k < 4; ++k) {
                s[k] = (k < nrem) ? src[p0 + k] : 0;
                d[k] = (k < nrem) ? dst[p0 + k] : 0;
            }
        }
    }

    gdc_wait();                  // T grid complete: g_T, cursor, counter ready

    if (nrem > 0) {
        float sum[4] = {0.f, 0.f, 0.f, 0.f};
#pragma unroll
        for (int l = 0; l < PATH_LEN; ++l) {
#pragma unroll
            for (int k = 0; k < 4; ++k) {
                const int* ik = (const int*)&pr[2 * k];
                int e = ik[l];
                if (e >= 0) sum[k] += __ldg(&g_T[(size_t)e * PATH_LEN + l]);
            }
        }
#pragma unroll
        for (int k = 0; k < 4; ++k) {
            if (k < nrem) {
                unsigned row = (unsigned)s[k];
                unsigned pos = atomicAdd(&g_cursor[row], 1u);
                if (pos < ROW_CAP) {
                    unsigned long long rec =
                        ((unsigned long long)(unsigned)(p0 + k + 1) << 44) |
                        ((unsigned long long)(unsigned)d[k] << 31) |
                        (unsigned long long)(__float_as_uint(sum[k]) >> 1);
                    g_rec[(size_t)row * ROW_CAP + pos] = rec;
                }
            }
        }
    }

    __syncthreads();
    if (threadIdx.x == 0) {
        __threadfence();                    // release records before count
        atomicAdd(&g_scatter_done, 1u);
    }
}

// ---------------------------------------------------------------------------
// 256 MB zero-fill, grid-stride streaming stores. Launched via PDL — co-runs
// with scatter (it depends on nothing). 4 CTAs/SM leaves room for scatter.
// ---------------------------------------------------------------------------
__global__ void __launch_bounds__(256)
fill_out(float4* __restrict__ p, size_t n4)
{
    size_t i      = (size_t)blockIdx.x * blockDim.x + threadIdx.x;
    size_t stride = (size_t)gridDim.x * blockDim.x;
    const float4 z = make_float4(0.f, 0.f, 0.f, 0.f);
    for (; i < n4; i += stride) __stcs(&p[i], z);
}

// ---------------------------------------------------------------------------
// One block per row: resolve winners in smem, write ONLY the ~122 winner
// cells (zeros already laid down by fill_out).
//   - stream edge guarantees fill_out complete; spin guarantees scatter
//     complete (PDL breaks transitive completion ordering).
// ---------------------------------------------------------------------------
__global__ void __launch_bounds__(256)
fixup_rows(float* __restrict__ out, unsigned n_scatter_blocks)
{
    __shared__ unsigned tag[N_NODES];   // 32 KB

    const unsigned row = blockIdx.x;
    const unsigned tid = threadIdx.x;

    uint4* tag4 = (uint4*)tag;
#pragma unroll
    for (int j = 0; j < (N_NODES / 4) / 256; ++j)
        tag4[tid + j * 256] = make_uint4(0u, 0u, 0u, 0u);

    if (tid == 0) {
        while (atomicAdd(&g_scatter_done, 0u) < n_scatter_blocks) { }
        __threadfence();                // acquire records/cursor
    }
    __syncthreads();

    unsigned cnt = g_cursor[row];
    if (cnt > ROW_CAP) cnt = ROW_CAP;

    unsigned col[2], pw[2], vb[2];
    bool have[2];
    const unsigned long long* rec = g_rec + (size_t)row * ROW_CAP;
#pragma unroll
    for (int q = 0; q < 2; ++q) {
        unsigned r = tid + q * 256;
        have[q] = (r < cnt);
        if (have[q]) {
            unsigned long long e = __ldg(&rec[r]);
            pw[q]  = (unsigned)(e >> 44);
            col[q] = (unsigned)(e >> 31) & 0x1FFFu;
            vb[q]  = ((unsigned)e & 0x7FFFFFFFu) << 1;
            atomicMax(&tag[col[q]], pw[q]);
        }
    }
    __syncthreads();

    float* orow = out + (size_t)row * N_NODES;
#pragma unroll
    for (int q = 0; q < 2; ++q)
        if (have[q] && tag[col[q]] == pw[q])        // unique winner
            orow[col[q]] = __uint_as_float(vb[q]);
}

// ---------------------------------------------------------------------------
extern "C" void kernel_launch(void* const* d_in, const int* in_sizes, int n_in,
                              void* d_out, int out_size)
{
    int off = (in_sizes[0] == 1) ? 1 : 0;

    const float* edge_attr   = (const float*)d_in[off + 0];
    const int*   src         = (const int*)  d_in[off + 1];
    const int*   dst         = (const int*)  d_in[off + 2];
    const int*   paths       = (const int*)  d_in[off + 3];
    const float* edge_vector = (const float*)d_in[off + 4];
    float* out = (float*)d_out;

    const int n_edges = in_sizes[off + 0] / EDGE_DIM;
    const int n_pairs = in_sizes[off + 1];

    // 1) T (plain)
    precompute_T<<<(n_edges + 255) / 256, 256>>>(edge_attr, edge_vector, n_edges);

    cudaLaunchAttribute attrs[1];
    attrs[0].id = cudaLaunchAttributeProgrammaticStreamSerialization;
    attrs[0].val.programmaticStreamSerializationAllowed = 1;

    // 2) scatter (PDL: preloads during T)
    const int n_thr = (n_pairs + 3) / 4;
    const unsigned n_scatter_blocks = (unsigned)((n_thr + 255) / 256);
    {
        cudaLaunchConfig_t cfg = {};
        cfg.gridDim  = dim3(n_scatter_blocks, 1, 1);
        cfg.blockDim = dim3(256, 1, 1);
        cfg.stream   = 0;
        cfg.attrs    = attrs;
        cfg.numAttrs = 1;
        cudaLaunchKernelEx(&cfg, scatter_dots4, paths, src, dst, n_pairs);
    }

    // 3) fill (PDL: launches at scatter entry -> overlaps gather phase)
    {
        cudaLaunchConfig_t cfg = {};
        cfg.gridDim  = dim3(592, 1, 1);      // 4 CTAs/SM, single wave
        cfg.blockDim = dim3(256, 1, 1);
        cfg.stream   = 0;
        cfg.attrs    = attrs;
        cfg.numAttrs = 1;
        size_t n4 = (size_t)out_size / 4;
        cudaLaunchKernelEx(&cfg, fill_out, (float4*)out, n4);
    }

    // 4) fixup (plain: waits fill completion via stream edge; scatter via spin)
    fixup_rows<<<N_NODES, 256>>>(out, n_scatter_blocks);
}

// round 17
// speedup vs baseline: 1.2452x; 1.2452x over previous
#include <cuda_runtime.h>
#include <cstdint>

#define N_NODES     8192
#define N_PAIRS_MAX 1000000
#define PATH_LEN    8
#define EDGE_DIM    16
#define MAX_EDGES   100000
#define ROW_CAP     512         // Poisson mean 122/row; 512 unreachable

// Record packing: [p+1 : 20][col : 13][val>>1 : 31]
//  - max over same-cell records == max over p+1 (top bits; col equal)
//  - val reconstructed as (low31 << 1): drops fp32 mantissa LSB (<=1 ulp)
__device__ float              g_T[MAX_EDGES * PATH_LEN];        // 3.2 MB
__device__ unsigned           g_cursor[N_NODES];                // 32 KB
__device__ unsigned long long g_rec[(size_t)N_NODES * ROW_CAP]; // 32 MB
__device__ unsigned           g_t_done = 0;                     // T-block counter

__device__ __forceinline__ void gdc_wait() {
    asm volatile("griddepcontrol.wait;" ::: "memory");
}
__device__ __forceinline__ void gdc_launch_dependents() {
    asm volatile("griddepcontrol.launch_dependents;" ::: "memory");
}

// ---------------------------------------------------------------------------
// Fused kernel: all blocks preload pair inputs; blocks 0..n_t_blocks-1 also
// compute the T table (T[e][l] = dot(edge_attr[e], edge_vector[l]) / L) and
// zero the cursor; everyone then spins on g_t_done before the gather phase.
// Deadlock-free: blocks issue in ascending bid order and the whole grid fits
// in wave 1 (977 blocks < 148 SMs * 7), so T blocks are resident immediately.
// ---------------------------------------------------------------------------
__global__ void __launch_bounds__(256)
scatter_fused(const float* __restrict__ edge_attr,
              const float* __restrict__ edge_vector,
              const int*   __restrict__ paths,
              const int*   __restrict__ src,
              const int*   __restrict__ dst,
              int n_edges, int n_pairs, int n_t_blocks)
{
    const int tid = threadIdx.x;
    const int bid = blockIdx.x;
    const int gt  = bid * 256 + tid;

    // ---- phase 0: preload pair inputs (no dependencies) ----
    int p0 = gt * 4;
    int nrem = n_pairs - p0;     // may be <= 0

    int4 pr[8];
    int s[4], d[4];
    if (nrem > 0) {
        const int4* pp = (const int4*)paths + (size_t)p0 * 2;
#pragma unroll
        for (int k = 0; k < 4; ++k) {
            if (k < nrem) {
                pr[2 * k + 0] = __ldg(&pp[2 * k + 0]);
                pr[2 * k + 1] = __ldg(&pp[2 * k + 1]);
            } else {
                pr[2 * k + 0] = make_int4(-1, -1, -1, -1);
                pr[2 * k + 1] = make_int4(-1, -1, -1, -1);
            }
        }
        if (nrem >= 4) {
            int4 s4 = __ldg((const int4*)(src + p0));
            int4 d4 = __ldg((const int4*)(dst + p0));
            s[0] = s4.x; s[1] = s4.y; s[2] = s4.z; s[3] = s4.w;
            d[0] = d4.x; d[1] = d4.y; d[2] = d4.z; d[3] = d4.w;
        } else {
#pragma unroll
            for (int k = 0; k < 4; ++k) {
                s[k] = (k < nrem) ? src[p0 + k] : 0;
                d[k] = (k < nrem) ? dst[p0 + k] : 0;
            }
        }
    }

    // ---- phase 1: T table + cursor zero (first n_t_blocks blocks) ----
    if (bid < n_t_blocks) {
        int e = gt;
        if (e < N_NODES) g_cursor[e] = 0u;
        if (e < n_edges) {
            const float4* ea = (const float4*)edge_attr + (size_t)e * 4;
            float4 a0 = __ldg(&ea[0]), a1 = __ldg(&ea[1]);
            float4 a2 = __ldg(&ea[2]), a3 = __ldg(&ea[3]);
            const float4* ev = (const float4*)edge_vector;
            float t[PATH_LEN];
#pragma unroll
            for (int l = 0; l < PATH_LEN; ++l) {
                float4 v0 = __ldg(&ev[l * 4 + 0]);
                float4 v1 = __ldg(&ev[l * 4 + 1]);
                float4 v2 = __ldg(&ev[l * 4 + 2]);
                float4 v3 = __ldg(&ev[l * 4 + 3]);
                float dd = a0.x * v0.x + a0.y * v0.y + a0.z * v0.z + a0.w * v0.w
                         + a1.x * v1.x + a1.y * v1.y + a1.z * v1.z + a1.w * v1.w
                         + a2.x * v2.x + a2.y * v2.y + a2.z * v2.z + a2.w * v2.w
                         + a3.x * v3.x + a3.y * v3.y + a3.z * v3.z + a3.w * v3.w;
                t[l] = dd * (1.0f / PATH_LEN);
            }
            float4* tt = (float4*)(g_T + (size_t)e * PATH_LEN);
            tt[0] = make_float4(t[0], t[1], t[2], t[3]);
            tt[1] = make_float4(t[4], t[5], t[6], t[7]);
        }
        __threadfence();             // release T rows + cursor zeros
        __syncthreads();             // whole block done before counting
        if (tid == 0) atomicAdd(&g_t_done, 1u);
    }

    // ---- phase 2: wait for full T table ----
    if (tid == 0) {
        while (atomicAdd(&g_t_done, 0u) < (unsigned)n_t_blocks) { }
    }
    __syncthreads();
    __threadfence();                 // acquire

    if (nrem > 0) {
        float sum[4] = {0.f, 0.f, 0.f, 0.f};
#pragma unroll
        for (int l = 0; l < PATH_LEN; ++l) {
#pragma unroll
            for (int k = 0; k < 4; ++k) {
                const int* ik = (const int*)&pr[2 * k];
                int e = ik[l];
                if (e >= 0) sum[k] += __ldg(&g_T[(size_t)e * PATH_LEN + l]);
            }
        }

        gdc_launch_dependents();     // write_rows may launch & zero smem now

#pragma unroll
        for (int k = 0; k < 4; ++k) {
            if (k < nrem) {
                unsigned row = (unsigned)s[k];
                unsigned pos = atomicAdd(&g_cursor[row], 1u);
                if (pos < ROW_CAP) {
                    unsigned long long rec =
                        ((unsigned long long)(unsigned)(p0 + k + 1) << 44) |
                        ((unsigned long long)(unsigned)d[k] << 31) |
                        (unsigned long long)(__float_as_uint(sum[k]) >> 1);
                    g_rec[(size_t)row * ROW_CAP + pos] = rec;
                }
            }
        }
    } else {
        gdc_launch_dependents();
    }
}

// ---------------------------------------------------------------------------
// One block (256 thr, 32KB smem) per row (R14 proven form). PDL: smem zeroing
// before the wait. Also resets g_t_done for the next graph replay.
//   Pass A: atomicMax(tag[col], p+1)   Pass B: winner installs val bits.
//   Safe: val_bits in [1,1e6] would mean |val| < 1.4e-39 (unreachable);
//   exact 0.0 -> bits 0 != any p+1.
// ---------------------------------------------------------------------------
__global__ void __launch_bounds__(256)
write_rows(float* __restrict__ out)
{
    __shared__ unsigned tag[N_NODES];   // 32 KB

    const unsigned row = blockIdx.x;
    const unsigned tid = threadIdx.x;

    uint4* tag4 = (uint4*)tag;
#pragma unroll
    for (int j = 0; j < (N_NODES / 4) / 256; ++j)
        tag4[tid + j * 256] = make_uint4(0u, 0u, 0u, 0u);

    gdc_wait();          // scatter grid complete
    __syncthreads();

    if (row == 0 && tid == 0) g_t_done = 0u;   // reset for next replay

    unsigned cnt = g_cursor[row];
    if (cnt > ROW_CAP) cnt = ROW_CAP;

    unsigned col[2], pw[2], vb[2];
    bool have[2];
    const unsigned long long* rec = g_rec + (size_t)row * ROW_CAP;
#pragma unroll
    for (int q = 0; q < 2; ++q) {
        unsigned r = tid + q * 256;
        have[q] = (r < cnt);
        if (have[q]) {
            unsigned long long e = __ldg(&rec[r]);
            pw[q]  = (unsigned)(e >> 44);
            col[q] = (unsigned)(e >> 31) & 0x1FFFu;
            vb[q]  = ((unsigned)e & 0x7FFFFFFFu) << 1;
            atomicMax(&tag[col[q]], pw[q]);
        }
    }
    __syncthreads();

#pragma unroll
    for (int q = 0; q < 2; ++q)
        if (have[q] && tag[col[q]] == pw[q]) tag[col[q]] = vb[q];
    __syncthreads();

    float4* orow = (float4*)(out + (size_t)row * N_NODES);
#pragma unroll
    for (int j = 0; j < (N_NODES / 4) / 256; ++j) {
        unsigned i = tid + j * 256;
        uint4 tv = tag4[i];
        float4 v;
        v.x = __uint_as_float(tv.x);
        v.y = __uint_as_float(tv.y);
        v.z = __uint_as_float(tv.z);
        v.w = __uint_as_float(tv.w);
        __stcs(&orow[i], v);
    }
}

// ---------------------------------------------------------------------------
extern "C" void kernel_launch(void* const* d_in, const int* in_sizes, int n_in,
                              void* d_out, int out_size)
{
    int off = (in_sizes[0] == 1) ? 1 : 0;

    const float* edge_attr   = (const float*)d_in[off + 0];
    const int*   src         = (const int*)  d_in[off + 1];
    const int*   dst         = (const int*)  d_in[off + 2];
    const int*   paths       = (const int*)  d_in[off + 3];
    const float* edge_vector = (const float*)d_in[off + 4];
    float* out = (float*)d_out;

    const int n_edges = in_sizes[off + 0] / EDGE_DIM;
    const int n_pairs = in_sizes[off + 1];

    const int n_thr      = (n_pairs + 3) / 4;
    const int n_blocks   = (n_thr + 255) / 256;           // 977
    const int n_t_blocks = (n_edges + 255) / 256;         // 391 (<= n_blocks)

    // 1) fused T + scatter (plain launch)
    scatter_fused<<<n_blocks, 256>>>(edge_attr, edge_vector, paths, src, dst,
                                     n_edges, n_pairs, n_t_blocks);

    // 2) write_rows (PDL-dependent on scatter)
    cudaLaunchAttribute attrs[1];
    attrs[0].id = cudaLaunchAttributeProgrammaticStreamSerialization;
    attrs[0].val.programmaticStreamSerializationAllowed = 1;

    cudaLaunchConfig_t cfg = {};
    cfg.gridDim  = dim3(N_NODES, 1, 1);
    cfg.blockDim = dim3(256, 1, 1);
    cfg.stream   = 0;
    cfg.attrs    = attrs;
    cfg.numAttrs = 1;
    cudaLaunchKernelEx(&cfg, write_rows, out);
}